// round 3
// baseline (speedup 1.0000x reference)
#include <cuda_runtime.h>
#include <math.h>

#define LSEQ 8192
#define EDIM 1024
#define NH   16
#define HD   64
#define CH   64
#define NW   (LSEQ/CH)

// Scratch (allocation-free rule: __device__ globals)
__device__ float g_q  [(size_t)LSEQ*EDIM];
__device__ float g_k  [(size_t)LSEQ*EDIM];
__device__ float g_v  [(size_t)LSEQ*EDIM];
__device__ float g_att[(size_t)LSEQ*EDIM];
__device__ float g_nrm[(size_t)LSEQ*EDIM];

// ---- packed f32x2 helpers (sm_100+; b64 registers as 2xf32 carriers) ----
typedef unsigned long long u64;
__device__ __forceinline__ u64 pk2(float x) {
    u64 d; asm("mov.b64 %0, {%1, %1};" : "=l"(d) : "f"(x)); return d;
}
__device__ __forceinline__ u64 ffma2(u64 a, u64 b, u64 c) {
    u64 d; asm("fma.rn.f32x2 %0, %1, %2, %3;" : "=l"(d) : "l"(a), "l"(b), "l"(c));
    return d;
}

// ============================================================================
// GEMM: C[m][n] = alpha * (sum_k A[m][k]*B[n][k] + bias[n])
// A: MxK row-major, B: NxK row-major (i.e. computes A @ B^T), C: MxN.
// 128x128 block tile, BK=16, 8x8 per-thread microtile, f32x2 packed math.
// ============================================================================
__global__ __launch_bounds__(256)
void gemm_abt(const float* __restrict__ A, const float* __restrict__ B,
              const float* __restrict__ bias, float* __restrict__ C,
              int M, int N, int K, float alpha)
{
    __shared__ float As[16][128];
    __shared__ float Bs[16][128];
    const int tid  = threadIdx.x;
    const int m0   = blockIdx.y * 128;
    const int n0   = blockIdx.x * 128;
    const int trow = tid >> 4;   // 0..15
    const int tcol = tid & 15;   // 0..15

    u64 acc[8][4];
    #pragma unroll
    for (int i = 0; i < 8; i++)
        #pragma unroll
        for (int j = 0; j < 4; j++) acc[i][j] = 0ull;

    const int r  = tid >> 2;          // 0..63
    const int c4 = (tid & 3) << 2;    // 0,4,8,12

    for (int k0 = 0; k0 < K; k0 += 16) {
        float4 ta0 = *(const float4*)(A + (size_t)(m0 + r     ) * K + k0 + c4);
        float4 ta1 = *(const float4*)(A + (size_t)(m0 + r + 64) * K + k0 + c4);
        float4 tb0 = *(const float4*)(B + (size_t)(n0 + r     ) * K + k0 + c4);
        float4 tb1 = *(const float4*)(B + (size_t)(n0 + r + 64) * K + k0 + c4);
        As[c4+0][r]    = ta0.x; As[c4+1][r]    = ta0.y; As[c4+2][r]    = ta0.z; As[c4+3][r]    = ta0.w;
        As[c4+0][r+64] = ta1.x; As[c4+1][r+64] = ta1.y; As[c4+2][r+64] = ta1.z; As[c4+3][r+64] = ta1.w;
        Bs[c4+0][r]    = tb0.x; Bs[c4+1][r]    = tb0.y; Bs[c4+2][r]    = tb0.z; Bs[c4+3][r]    = tb0.w;
        Bs[c4+0][r+64] = tb1.x; Bs[c4+1][r+64] = tb1.y; Bs[c4+2][r+64] = tb1.z; Bs[c4+3][r+64] = tb1.w;
        __syncthreads();

        #pragma unroll
        for (int kk = 0; kk < 16; kk++) {
            float ra[8];
            *(float4*)&ra[0] = *(const float4*)&As[kk][trow*8];
            *(float4*)&ra[4] = *(const float4*)&As[kk][trow*8 + 4];
            u64 rb[4];
            *(ulonglong2*)&rb[0] = *(const ulonglong2*)&Bs[kk][tcol*8];
            *(ulonglong2*)&rb[2] = *(const ulonglong2*)&Bs[kk][tcol*8 + 4];
            #pragma unroll
            for (int i = 0; i < 8; i++) {
                u64 ai = pk2(ra[i]);
                #pragma unroll
                for (int j = 0; j < 4; j++)
                    acc[i][j] = ffma2(ai, rb[j], acc[i][j]);
            }
        }
        __syncthreads();
    }

    #pragma unroll
    for (int i = 0; i < 8; i++) {
        const float* f = (const float*)acc[i];   // 4 u64 -> 8 floats, j-order
        const int m = m0 + trow*8 + i;
        #pragma unroll
        for (int j = 0; j < 8; j += 4) {
            const int n = n0 + tcol*8 + j;
            float4 o;
            o.x = alpha * (f[j+0] + bias[n+0]);
            o.y = alpha * (f[j+1] + bias[n+1]);
            o.z = alpha * (f[j+2] + bias[n+2]);
            o.w = alpha * (f[j+3] + bias[n+3]);
            *(float4*)(C + (size_t)m * N + n) = o;
        }
    }
}

// ============================================================================
// Local chunked relu-attention.
// Block = (window w, head h). out[64,64] = sum over chunks cw in {w-1,w,w+1}
// of relu(q_tile @ k_chunk^T) @ v_chunk.  Zero-padded chunks contribute 0
// exactly (relu(q.0)=0, v rows = 0), so out-of-range chunks are just skipped.
// Shared: qT (transposed, swizzled) + kT/v union + s — exactly 48KB.
// ============================================================================
#define SWZC(g,e) ((((g) ^ ((e) & 15)) << 2))

__global__ __launch_bounds__(256)
void local_attn(const float* __restrict__ Q, const float* __restrict__ Km,
                const float* __restrict__ Vm, float* __restrict__ O)
{
    __shared__ float qT[64][64];   // [e][i], float4-group swizzled by e
    __shared__ float kv[64][64];   // kT [e][j] swizzled in s-phase; v [j][e] plain in acc phase
    __shared__ float ss[64][64];   // relu(scores) [i][j]
    const int w   = blockIdx.x;
    const int h   = blockIdx.y;
    const int tid = threadIdx.x;
    const int tx  = tid & 15;      // j / e tile coord
    const int ty  = tid >> 4;      // i tile coord
    const int cb  = h * HD;

    // load q tile transposed: qT[e][i]
    #pragma unroll
    for (int l = 0; l < 4; l++) {
        int idx = tid + l * 256;
        int i   = idx >> 4;
        int e4  = (idx & 15) << 2;
        float4 t = *(const float4*)(Q + (size_t)(w*CH + i)*EDIM + cb + e4);
        int g = i >> 2, im = i & 3;
        qT[e4+0][SWZC(g, e4+0) + im] = t.x;
        qT[e4+1][SWZC(g, e4+1) + im] = t.y;
        qT[e4+2][SWZC(g, e4+2) + im] = t.z;
        qT[e4+3][SWZC(g, e4+3) + im] = t.w;
    }

    float o[4][4] = {};

    for (int cw = w - 1; cw <= w + 1; cw++) {
        if (cw < 0 || cw >= NW) continue;          // uniform per block
        __syncthreads();                           // prev-iter readers done; qT ready (1st)

        // load k chunk transposed+swizzled: kv[e][j]
        #pragma unroll
        for (int l = 0; l < 4; l++) {
            int idx = tid + l * 256;
            int j   = idx >> 4;
            int e4  = (idx & 15) << 2;
            float4 t = *(const float4*)(Km + (size_t)(cw*CH + j)*EDIM + cb + e4);
            int g = j >> 2, jm = j & 3;
            kv[e4+0][SWZC(g, e4+0) + jm] = t.x;
            kv[e4+1][SWZC(g, e4+1) + jm] = t.y;
            kv[e4+2][SWZC(g, e4+2) + jm] = t.z;
            kv[e4+3][SWZC(g, e4+3) + jm] = t.w;
        }
        __syncthreads();

        // s[i][j] = sum_e q[i][e] * k[j][e]
        float s[4][4] = {};
        #pragma unroll 8
        for (int e = 0; e < 64; e++) {
            float4 a = *(const float4*)&qT[e][SWZC(ty, e)];
            float4 b = *(const float4*)&kv[e][SWZC(tx, e)];
            float av[4] = {a.x, a.y, a.z, a.w};
            float bv[4] = {b.x, b.y, b.z, b.w};
            #pragma unroll
            for (int rr = 0; rr < 4; rr++)
                #pragma unroll
                for (int cc = 0; cc < 4; cc++)
                    s[rr][cc] += av[rr] * bv[cc];
        }
        #pragma unroll
        for (int rr = 0; rr < 4; rr++)
            #pragma unroll
            for (int cc = 0; cc < 4; cc++)
                ss[ty*4+rr][tx*4+cc] = fmaxf(s[rr][cc], 0.0f);
        __syncthreads();                           // ss ready; kT reads done

        // load v chunk plain: kv[j][e]
        #pragma unroll
        for (int l = 0; l < 4; l++) {
            int idx = tid + l * 256;
            int j   = idx >> 4;
            int e4  = (idx & 15) << 2;
            *(float4*)&kv[j][e4] =
                *(const float4*)(Vm + (size_t)(cw*CH + j)*EDIM + cb + e4);
        }
        __syncthreads();

        // o[i][e] += sum_j ss[i][j] * v[j][e]
        #pragma unroll 8
        for (int j = 0; j < 64; j++) {
            float4 vv = *(const float4*)&kv[j][tx*4];
            float s0 = ss[ty*4+0][j];
            float s1 = ss[ty*4+1][j];
            float s2 = ss[ty*4+2][j];
            float s3 = ss[ty*4+3][j];
            o[0][0] += s0*vv.x; o[0][1] += s0*vv.y; o[0][2] += s0*vv.z; o[0][3] += s0*vv.w;
            o[1][0] += s1*vv.x; o[1][1] += s1*vv.y; o[1][2] += s1*vv.z; o[1][3] += s1*vv.w;
            o[2][0] += s2*vv.x; o[2][1] += s2*vv.y; o[2][2] += s2*vv.z; o[2][3] += s2*vv.w;
            o[3][0] += s3*vv.x; o[3][1] += s3*vv.y; o[3][2] += s3*vv.z; o[3][3] += s3*vv.w;
        }
    }

    #pragma unroll
    for (int rr = 0; rr < 4; rr++) {
        float4 t = make_float4(o[rr][0], o[rr][1], o[rr][2], o[rr][3]);
        *(float4*)(O + (size_t)(w*CH + ty*4 + rr)*EDIM + cb + tx*4) = t;
    }
}

// ============================================================================
// Gated RMSNorm over E=1024: y = scale * (x / (rms + 1e-8)) * sigmoid(gate*x)
// One block per row, 256 threads, 1 float4 per thread.
// ============================================================================
__global__ __launch_bounds__(256)
void rms_gate(const float* __restrict__ X, const float* __restrict__ sc,
              const float* __restrict__ gt, float* __restrict__ Y)
{
    __shared__ float red[8];
    const int row = blockIdx.x;
    const int tid = threadIdx.x;
    float4 x = ((const float4*)(X + (size_t)row * EDIM))[tid];
    float ssq = x.x*x.x + x.y*x.y + x.z*x.z + x.w*x.w;
    #pragma unroll
    for (int d = 16; d; d >>= 1) ssq += __shfl_xor_sync(0xffffffffu, ssq, d);
    if ((tid & 31) == 0) red[tid >> 5] = ssq;
    __syncthreads();
    if (tid < 32) {
        float t = (tid < 8) ? red[tid] : 0.0f;
        #pragma unroll
        for (int d = 4; d; d >>= 1) t += __shfl_xor_sync(0xffffffffu, t, d);
        if (tid == 0) red[0] = t;
    }
    __syncthreads();
    const float rms = sqrtf(red[0] * (1.0f / EDIM));
    const float inv = 1.0f / (rms + 1e-8f);
    const int c = tid << 2;
    float4 s4 = *(const float4*)(sc + c);
    float4 g4 = *(const float4*)(gt + c);
    float4 y;
    y.x = s4.x * x.x * inv * (1.0f / (1.0f + __expf(-g4.x * x.x)));
    y.y = s4.y * x.y * inv * (1.0f / (1.0f + __expf(-g4.y * x.y)));
    y.z = s4.z * x.z * inv * (1.0f / (1.0f + __expf(-g4.z * x.z)));
    y.w = s4.w * x.w * inv * (1.0f / (1.0f + __expf(-g4.w * x.w)));
    ((float4*)(Y + (size_t)row * EDIM))[tid] = y;
}

// ============================================================================
extern "C" void kernel_launch(void* const* d_in, const int* in_sizes, int n_in,
                              void* d_out, int out_size)
{
    const float* query = (const float*)d_in[0];
    const float* key_  = (const float*)d_in[1];
    const float* value = (const float*)d_in[2];
    const float* w_q   = (const float*)d_in[3];
    const float* b_q   = (const float*)d_in[4];
    const float* w_k   = (const float*)d_in[5];
    const float* b_k   = (const float*)d_in[6];
    const float* w_v   = (const float*)d_in[7];
    const float* b_v   = (const float*)d_in[8];
    const float* w_o   = (const float*)d_in[9];
    const float* b_o   = (const float*)d_in[10];
    const float* nsc   = (const float*)d_in[11];
    const float* ngt   = (const float*)d_in[12];
    float* out = (float*)d_out;

    void *pq, *pk, *pv, *pa, *pn;
    cudaGetSymbolAddress(&pq, g_q);
    cudaGetSymbolAddress(&pk, g_k);
    cudaGetSymbolAddress(&pv, g_v);
    cudaGetSymbolAddress(&pa, g_att);
    cudaGetSymbolAddress(&pn, g_nrm);
    float* gq = (float*)pq;
    float* gk = (float*)pk;
    float* gv = (float*)pv;
    float* ga = (float*)pa;
    float* gn = (float*)pn;

    const dim3 ggrd(EDIM/128, LSEQ/128);   // (8, 64)
    const float scaling = 0.125f;          // HD^-0.5

    gemm_abt<<<ggrd, 256>>>(query, w_q, b_q, gq, LSEQ, EDIM, EDIM, scaling);
    gemm_abt<<<ggrd, 256>>>(key_,  w_k, b_k, gk, LSEQ, EDIM, EDIM, 1.0f);
    gemm_abt<<<ggrd, 256>>>(value, w_v, b_v, gv, LSEQ, EDIM, EDIM, 1.0f);

    local_attn<<<dim3(NW, NH), 256>>>(gq, gk, gv, ga);

    rms_gate<<<LSEQ, 256>>>(ga, nsc, ngt, gn);

    gemm_abt<<<ggrd, 256>>>(gn, w_o, b_o, out, LSEQ, EDIM, EDIM, 1.0f);
}

// round 5
// speedup vs baseline: 2.5237x; 2.5237x over previous
#include <cuda_runtime.h>
#include <cuda_bf16.h>
#include <math.h>

#define LSEQ 8192
#define EDIM 1024
#define NH   16
#define HD   64
#define CH   64
#define NW   (LSEQ/CH)

typedef unsigned int       u32;
typedef unsigned long long u64;

// ---------------- scratch (__device__ globals; no allocation) ----------------
__device__ float g_q  [(size_t)LSEQ*EDIM];
__device__ float g_k  [(size_t)LSEQ*EDIM];
__device__ float g_v  [(size_t)LSEQ*EDIM];
__device__ float g_att[(size_t)LSEQ*EDIM];
__device__ __nv_bfloat16 g_ah[(size_t)LSEQ*EDIM];
__device__ __nv_bfloat16 g_al[(size_t)LSEQ*EDIM];
__device__ __nv_bfloat16 g_wh[(size_t)EDIM*EDIM];
__device__ __nv_bfloat16 g_wl[(size_t)EDIM*EDIM];

// ---------------- PTX helpers (all baseline sm_80-class; no 'a' variants) ----
__device__ __forceinline__ u32 s2u(const void* p) {
    u32 a; asm("{ .reg .u64 t; cvta.to.shared.u64 t, %1; cvt.u32.u64 %0, t; }" : "=r"(a) : "l"(p));
    return a;
}
__device__ __forceinline__ void cpa16(u32 dst, const void* src) {
    asm volatile("cp.async.cg.shared.global [%0], [%1], 16;" :: "r"(dst), "l"(src) : "memory");
}
__device__ __forceinline__ void cpa_commit() {
    asm volatile("cp.async.commit_group;" ::: "memory");
}
__device__ __forceinline__ void cpa_wait1() {
    asm volatile("cp.async.wait_group 1;" ::: "memory");
}
__device__ __forceinline__ void ldm4(u32* r, u32 addr) {
    asm volatile("ldmatrix.sync.aligned.m8n8.x4.shared.b16 {%0,%1,%2,%3}, [%4];"
                 : "=r"(r[0]), "=r"(r[1]), "=r"(r[2]), "=r"(r[3]) : "r"(addr));
}
__device__ __forceinline__ void mma_bf16(float* c, const u32* a, u32 b0, u32 b1) {
    asm volatile("mma.sync.aligned.m16n8k16.row.col.f32.bf16.bf16.f32 "
                 "{%0,%1,%2,%3}, {%4,%5,%6,%7}, {%8,%9}, {%0,%1,%2,%3};"
                 : "+f"(c[0]), "+f"(c[1]), "+f"(c[2]), "+f"(c[3])
                 : "r"(a[0]), "r"(a[1]), "r"(a[2]), "r"(a[3]), "r"(b0), "r"(b1));
}

// ============================================================================
// Tensor-core GEMM via mma.sync:  C[m][n] = alpha*(sum_k A[m][k]*B[n][k] + bias[n])
// A,B as bf16 hi/lo pairs; acc = Ah*Bh + Ah*Bl + Al*Bh in fp32 regs.
// BM=BN=128, BK=64; 8 warps, warp tile 32x64; cp.async double buffer.
// SMEM tiles: 128 rows x 128B (64 bf16), swizzle off = row*128 + 16*(c16^(row&7)).
// ============================================================================
#define BM 128
#define BN 128
#define BK 64
#define NCHUNK (EDIM/BK)        // 16
#define TILE_B (BM*BK*2)        // 16384 bytes per sub-tile
#define BUF_B  (4*TILE_B)       // Ah, Al, Bh, Bl
#define SMEM_DYN (1024 + 2*BUF_B)

__global__ void __launch_bounds__(256, 1)
tc_gemm(const __nv_bfloat16* __restrict__ Ah, const __nv_bfloat16* __restrict__ Al,
        const __nv_bfloat16* __restrict__ Bh, const __nv_bfloat16* __restrict__ Bl,
        const float* __restrict__ bias, float* __restrict__ C, float alpha)
{
    extern __shared__ char smem_raw[];
    const u32 bufbase = (s2u(smem_raw) + 1023u) & ~1023u;
    const int tid  = threadIdx.x;
    const int wid  = tid >> 5, lane = tid & 31;
    const int m0   = blockIdx.y * BM, n0 = blockIdx.x * BN;
    const int wm   = (wid & 3) * 32;      // warp M offset in tile
    const int wn   = (wid >> 2) * 64;     // warp N offset in tile

    const __nv_bfloat16* s0 = Ah + (size_t)m0 * EDIM;
    const __nv_bfloat16* s1 = Al + (size_t)m0 * EDIM;
    const __nv_bfloat16* s2 = Bh + (size_t)n0 * EDIM;
    const __nv_bfloat16* s3 = Bl + (size_t)n0 * EDIM;

    auto load_chunk = [&](int c, int buf) {
        const u32 base = bufbase + buf * BUF_B;
        const int k0 = c * BK;
        #pragma unroll
        for (int it = 0; it < 4; it++) {
            int seg = tid + it * 256;              // 0..1023
            int r   = seg >> 3;                    // row 0..127
            int c16 = seg & 7;                     // 16B col
            u32 sw  = (u32)(r * 128 + 16 * (c16 ^ (r & 7)));
            size_t g = (size_t)r * EDIM + k0 + c16 * 8;
            cpa16(base + sw,            s0 + g);
            cpa16(base + TILE_B   + sw, s1 + g);
            cpa16(base + 2*TILE_B + sw, s2 + g);
            cpa16(base + 3*TILE_B + sw, s3 + g);
        }
    };

    float acc[16][4];
    #pragma unroll
    for (int i = 0; i < 16; i++)
        #pragma unroll
        for (int j = 0; j < 4; j++) acc[i][j] = 0.0f;

    load_chunk(0, 0); cpa_commit();
    load_chunk(1, 1); cpa_commit();

    // per-lane fragment address components (row-within-tile, 16B col index)
    const int a_row = ((lane >> 3) & 1) * 8 + (lane & 7);
    const int a_cs  = (lane >> 4) & 1;
    const int b_row = ((lane >> 4) & 1) * 8 + (lane & 7);
    const int b_cs  = (lane >> 3) & 1;

    for (int c = 0; c < NCHUNK; c++) {
        cpa_wait1();
        __syncthreads();

        const u32 base = bufbase + (c & 1) * BUF_B;
        const u32 bAh = base, bAl = base + TILE_B;
        const u32 bBh = base + 2*TILE_B, bBl = base + 3*TILE_B;

        #pragma unroll
        for (int ks4 = 0; ks4 < 4; ks4++) {      // four k16 steps in BK=64
            const int ks = 2 * ks4;
            u32 ah[2][4], al[2][4];
            #pragma unroll
            for (int mt = 0; mt < 2; mt++) {
                int row = wm + mt * 16 + a_row;
                u32 off = (u32)(row * 128 + 16 * ((ks + a_cs) ^ (row & 7)));
                ldm4(ah[mt], bAh + off);
                ldm4(al[mt], bAl + off);
            }
            #pragma unroll
            for (int nt2 = 0; nt2 < 4; nt2++) {  // four n16 groups (8 n8 tiles)
                int row = wn + nt2 * 16 + b_row;
                u32 off = (u32)(row * 128 + 16 * ((ks + b_cs) ^ (row & 7)));
                u32 bh[4], bl[4];
                ldm4(bh, bBh + off);
                ldm4(bl, bBl + off);
                #pragma unroll
                for (int jj = 0; jj < 2; jj++)
                    #pragma unroll
                    for (int mt = 0; mt < 2; mt++) {
                        float* cc = acc[(nt2*2 + jj)*2 + mt];
                        mma_bf16(cc, ah[mt], bh[2*jj], bh[2*jj+1]);
                        mma_bf16(cc, ah[mt], bl[2*jj], bl[2*jj+1]);
                        mma_bf16(cc, al[mt], bh[2*jj], bh[2*jj+1]);
                    }
            }
        }
        __syncthreads();
        if (c + 2 < NCHUNK) load_chunk(c + 2, c & 1);
        cpa_commit();                            // possibly-empty group keeps count invariant
    }

    // epilogue: fragment -> global, with bias and alpha
    const int qr = lane >> 2;            // 0..7
    const int qc = (lane & 3) * 2;       // 0,2,4,6
    #pragma unroll
    for (int nt = 0; nt < 8; nt++) {
        #pragma unroll
        for (int mt = 0; mt < 2; mt++) {
            const float* cc = acc[nt*2 + mt];
            const int col = n0 + wn + nt*8 + qc;
            const float b0 = bias[col], b1 = bias[col+1];
            const int r0 = m0 + wm + mt*16 + qr;
            float2 o0 = make_float2(alpha*(cc[0]+b0), alpha*(cc[1]+b1));
            float2 o1 = make_float2(alpha*(cc[2]+b0), alpha*(cc[3]+b1));
            *(float2*)(C + (size_t)r0       * EDIM + col) = o0;
            *(float2*)(C + (size_t)(r0 + 8) * EDIM + col) = o1;
        }
    }
}

// ============================================================================
// fp32 -> bf16 hi/lo split (x = hi + lo, lo = bf16(x - hi))
// ============================================================================
__global__ void __launch_bounds__(256)
cvt_hilo(const float* __restrict__ X, __nv_bfloat16* __restrict__ H,
         __nv_bfloat16* __restrict__ L, int n4)
{
    int i = blockIdx.x * blockDim.x + threadIdx.x;
    if (i >= n4) return;
    float4 x = ((const float4*)X)[i];
    __nv_bfloat16 h0 = __float2bfloat16(x.x), h1 = __float2bfloat16(x.y);
    __nv_bfloat16 h2 = __float2bfloat16(x.z), h3 = __float2bfloat16(x.w);
    __nv_bfloat16 l0 = __float2bfloat16(x.x - __bfloat162float(h0));
    __nv_bfloat16 l1 = __float2bfloat16(x.y - __bfloat162float(h1));
    __nv_bfloat16 l2 = __float2bfloat16(x.z - __bfloat162float(h2));
    __nv_bfloat16 l3 = __float2bfloat16(x.w - __bfloat162float(h3));
    __nv_bfloat162 hA; hA.x = h0; hA.y = h1;
    __nv_bfloat162 hB; hB.x = h2; hB.y = h3;
    __nv_bfloat162 lA; lA.x = l0; lA.y = l1;
    __nv_bfloat162 lB; lB.x = l2; lB.y = l3;
    ((__nv_bfloat162*)H)[2*i]   = hA; ((__nv_bfloat162*)H)[2*i+1] = hB;
    ((__nv_bfloat162*)L)[2*i]   = lA; ((__nv_bfloat162*)L)[2*i+1] = lB;
}

// ============================================================================
// Local chunked relu-attention (R3 version — 215us, fp32 exact)
// ============================================================================
#define SWZC(g,e) ((((g) ^ ((e) & 15)) << 2))

__global__ void __launch_bounds__(256)
local_attn(const float* __restrict__ Q, const float* __restrict__ Km,
           const float* __restrict__ Vm, float* __restrict__ O)
{
    __shared__ float qT[64][64];
    __shared__ float kv[64][64];
    __shared__ float ss[64][64];
    const int w   = blockIdx.x;
    const int h   = blockIdx.y;
    const int tid = threadIdx.x;
    const int tx  = tid & 15;
    const int ty  = tid >> 4;
    const int cb  = h * HD;

    #pragma unroll
    for (int l = 0; l < 4; l++) {
        int idx = tid + l * 256;
        int i   = idx >> 4;
        int e4  = (idx & 15) << 2;
        float4 t = *(const float4*)(Q + (size_t)(w*CH + i)*EDIM + cb + e4);
        int g = i >> 2, im = i & 3;
        qT[e4+0][SWZC(g, e4+0) + im] = t.x;
        qT[e4+1][SWZC(g, e4+1) + im] = t.y;
        qT[e4+2][SWZC(g, e4+2) + im] = t.z;
        qT[e4+3][SWZC(g, e4+3) + im] = t.w;
    }

    float o[4][4] = {};

    for (int cw = w - 1; cw <= w + 1; cw++) {
        if (cw < 0 || cw >= NW) continue;
        __syncthreads();

        #pragma unroll
        for (int l = 0; l < 4; l++) {
            int idx = tid + l * 256;
            int j   = idx >> 4;
            int e4  = (idx & 15) << 2;
            float4 t = *(const float4*)(Km + (size_t)(cw*CH + j)*EDIM + cb + e4);
            int g = j >> 2, jm = j & 3;
            kv[e4+0][SWZC(g, e4+0) + jm] = t.x;
            kv[e4+1][SWZC(g, e4+1) + jm] = t.y;
            kv[e4+2][SWZC(g, e4+2) + jm] = t.z;
            kv[e4+3][SWZC(g, e4+3) + jm] = t.w;
        }
        __syncthreads();

        float s[4][4] = {};
        #pragma unroll 8
        for (int e = 0; e < 64; e++) {
            float4 a = *(const float4*)&qT[e][SWZC(ty, e)];
            float4 b = *(const float4*)&kv[e][SWZC(tx, e)];
            float av[4] = {a.x, a.y, a.z, a.w};
            float bv[4] = {b.x, b.y, b.z, b.w};
            #pragma unroll
            for (int rr = 0; rr < 4; rr++)
                #pragma unroll
                for (int cc = 0; cc < 4; cc++)
                    s[rr][cc] += av[rr] * bv[cc];
        }
        #pragma unroll
        for (int rr = 0; rr < 4; rr++)
            #pragma unroll
            for (int cc = 0; cc < 4; cc++)
                ss[ty*4+rr][tx*4+cc] = fmaxf(s[rr][cc], 0.0f);
        __syncthreads();

        #pragma unroll
        for (int l = 0; l < 4; l++) {
            int idx = tid + l * 256;
            int j   = idx >> 4;
            int e4  = (idx & 15) << 2;
            *(float4*)&kv[j][e4] =
                *(const float4*)(Vm + (size_t)(cw*CH + j)*EDIM + cb + e4);
        }
        __syncthreads();

        #pragma unroll 8
        for (int j = 0; j < 64; j++) {
            float4 vv = *(const float4*)&kv[j][tx*4];
            float s0 = ss[ty*4+0][j];
            float s1 = ss[ty*4+1][j];
            float s2 = ss[ty*4+2][j];
            float s3 = ss[ty*4+3][j];
            o[0][0] += s0*vv.x; o[0][1] += s0*vv.y; o[0][2] += s0*vv.z; o[0][3] += s0*vv.w;
            o[1][0] += s1*vv.x; o[1][1] += s1*vv.y; o[1][2] += s1*vv.z; o[1][3] += s1*vv.w;
            o[2][0] += s2*vv.x; o[2][1] += s2*vv.y; o[2][2] += s2*vv.z; o[2][3] += s2*vv.w;
            o[3][0] += s3*vv.x; o[3][1] += s3*vv.y; o[3][2] += s3*vv.z; o[3][3] += s3*vv.w;
        }
    }

    #pragma unroll
    for (int rr = 0; rr < 4; rr++) {
        float4 t = make_float4(o[rr][0], o[rr][1], o[rr][2], o[rr][3]);
        *(float4*)(O + (size_t)(w*CH + ty*4 + rr)*EDIM + cb + tx*4) = t;
    }
}

// ============================================================================
// Gated RMSNorm -> bf16 hi/lo output (feeds output-projection tc_gemm)
// ============================================================================
__global__ void __launch_bounds__(256)
rms_gate_bf(const float* __restrict__ X, const float* __restrict__ sc,
            const float* __restrict__ gt, __nv_bfloat16* __restrict__ H,
            __nv_bfloat16* __restrict__ L)
{
    __shared__ float red[8];
    const int row = blockIdx.x;
    const int tid = threadIdx.x;
    float4 x = ((const float4*)(X + (size_t)row * EDIM))[tid];
    float ssq = x.x*x.x + x.y*x.y + x.z*x.z + x.w*x.w;
    #pragma unroll
    for (int d = 16; d; d >>= 1) ssq += __shfl_xor_sync(0xffffffffu, ssq, d);
    if ((tid & 31) == 0) red[tid >> 5] = ssq;
    __syncthreads();
    if (tid < 32) {
        float t = (tid < 8) ? red[tid] : 0.0f;
        #pragma unroll
        for (int d = 4; d; d >>= 1) t += __shfl_xor_sync(0xffffffffu, t, d);
        if (tid == 0) red[0] = t;
    }
    __syncthreads();
    const float rms = sqrtf(red[0] * (1.0f / EDIM));
    const float inv = 1.0f / (rms + 1e-8f);
    const int c = tid << 2;
    float4 s4 = *(const float4*)(sc + c);
    float4 g4 = *(const float4*)(gt + c);
    float y0 = s4.x * x.x * inv * (1.0f / (1.0f + __expf(-g4.x * x.x)));
    float y1 = s4.y * x.y * inv * (1.0f / (1.0f + __expf(-g4.y * x.y)));
    float y2 = s4.z * x.z * inv * (1.0f / (1.0f + __expf(-g4.z * x.z)));
    float y3 = s4.w * x.w * inv * (1.0f / (1.0f + __expf(-g4.w * x.w)));
    __nv_bfloat16 h0 = __float2bfloat16(y0), h1 = __float2bfloat16(y1);
    __nv_bfloat16 h2 = __float2bfloat16(y2), h3 = __float2bfloat16(y3);
    __nv_bfloat16 l0 = __float2bfloat16(y0 - __bfloat162float(h0));
    __nv_bfloat16 l1 = __float2bfloat16(y1 - __bfloat162float(h1));
    __nv_bfloat16 l2 = __float2bfloat16(y2 - __bfloat162float(h2));
    __nv_bfloat16 l3 = __float2bfloat16(y3 - __bfloat162float(h3));
    size_t base = (size_t)row * EDIM + c;
    __nv_bfloat162 hA; hA.x = h0; hA.y = h1;
    __nv_bfloat162 hB; hB.x = h2; hB.y = h3;
    __nv_bfloat162 lA; lA.x = l0; lA.y = l1;
    __nv_bfloat162 lB; lB.x = l2; lB.y = l3;
    *(__nv_bfloat162*)(H + base)     = hA;
    *(__nv_bfloat162*)(H + base + 2) = hB;
    *(__nv_bfloat162*)(L + base)     = lA;
    *(__nv_bfloat162*)(L + base + 2) = lB;
}

// ============================================================================
extern "C" void kernel_launch(void* const* d_in, const int* in_sizes, int n_in,
                              void* d_out, int out_size)
{
    const float* query = (const float*)d_in[0];
    const float* key_  = (const float*)d_in[1];
    const float* value = (const float*)d_in[2];
    const float* w_q   = (const float*)d_in[3];
    const float* b_q   = (const float*)d_in[4];
    const float* w_k   = (const float*)d_in[5];
    const float* b_k   = (const float*)d_in[6];
    const float* w_v   = (const float*)d_in[7];
    const float* b_v   = (const float*)d_in[8];
    const float* w_o   = (const float*)d_in[9];
    const float* b_o   = (const float*)d_in[10];
    const float* nsc   = (const float*)d_in[11];
    const float* ngt   = (const float*)d_in[12];
    float* out = (float*)d_out;

    void *pq, *pk, *pv, *pa, *pah, *pal, *pwh, *pwl;
    cudaGetSymbolAddress(&pq,  g_q);
    cudaGetSymbolAddress(&pk,  g_k);
    cudaGetSymbolAddress(&pv,  g_v);
    cudaGetSymbolAddress(&pa,  g_att);
    cudaGetSymbolAddress(&pah, g_ah);
    cudaGetSymbolAddress(&pal, g_al);
    cudaGetSymbolAddress(&pwh, g_wh);
    cudaGetSymbolAddress(&pwl, g_wl);
    float* gq = (float*)pq;
    float* gk = (float*)pk;
    float* gv = (float*)pv;
    float* ga = (float*)pa;
    __nv_bfloat16* ah = (__nv_bfloat16*)pah;
    __nv_bfloat16* al = (__nv_bfloat16*)pal;
    __nv_bfloat16* wh = (__nv_bfloat16*)pwh;
    __nv_bfloat16* wl = (__nv_bfloat16*)pwl;

    cudaFuncSetAttribute(tc_gemm, cudaFuncAttributeMaxDynamicSharedMemorySize, SMEM_DYN);

    const dim3 ggrd(EDIM/BN, LSEQ/BM);   // (8, 64)
    const int nA4 = LSEQ*EDIM/4;
    const int nW4 = EDIM*EDIM/4;
    const float scaling = 0.125f;        // HD^-0.5

    cvt_hilo<<<nA4/256, 256>>>(query, ah, al, nA4);
    cvt_hilo<<<nW4/256, 256>>>(w_q,   wh, wl, nW4);
    tc_gemm<<<ggrd, 256, SMEM_DYN>>>(ah, al, wh, wl, b_q, gq, scaling);

    cvt_hilo<<<nA4/256, 256>>>(key_,  ah, al, nA4);
    cvt_hilo<<<nW4/256, 256>>>(w_k,   wh, wl, nW4);
    tc_gemm<<<ggrd, 256, SMEM_DYN>>>(ah, al, wh, wl, b_k, gk, 1.0f);

    cvt_hilo<<<nA4/256, 256>>>(value, ah, al, nA4);
    cvt_hilo<<<nW4/256, 256>>>(w_v,   wh, wl, nW4);
    tc_gemm<<<ggrd, 256, SMEM_DYN>>>(ah, al, wh, wl, b_v, gv, 1.0f);

    local_attn<<<dim3(NW, NH), 256>>>(gq, gk, gv, ga);

    rms_gate_bf<<<LSEQ, 256>>>(ga, nsc, ngt, ah, al);

    cvt_hilo<<<nW4/256, 256>>>(w_o, wh, wl, nW4);
    tc_gemm<<<ggrd, 256, SMEM_DYN>>>(ah, al, wh, wl, b_o, out, 1.0f);
}

// round 6
// speedup vs baseline: 2.6520x; 1.0509x over previous
#include <cuda_runtime.h>
#include <cuda_bf16.h>
#include <math.h>

#define LSEQ 8192
#define EDIM 1024
#define NH   16
#define HD   64
#define CH   64
#define NW   (LSEQ/CH)

typedef unsigned int       u32;
typedef unsigned long long u64;

// ---------------- scratch (__device__ globals; no allocation) ----------------
__device__ float g_q  [(size_t)LSEQ*EDIM];
__device__ float g_k  [(size_t)LSEQ*EDIM];
__device__ float g_v  [(size_t)LSEQ*EDIM];
__device__ float g_att[(size_t)LSEQ*EDIM];
__device__ __nv_bfloat16 g_aqh[(size_t)LSEQ*EDIM], g_aql[(size_t)LSEQ*EDIM];
__device__ __nv_bfloat16 g_akh[(size_t)LSEQ*EDIM], g_akl[(size_t)LSEQ*EDIM];
__device__ __nv_bfloat16 g_avh[(size_t)LSEQ*EDIM], g_avl[(size_t)LSEQ*EDIM];
__device__ __nv_bfloat16 g_wqh[(size_t)EDIM*EDIM], g_wql[(size_t)EDIM*EDIM];
__device__ __nv_bfloat16 g_wkh[(size_t)EDIM*EDIM], g_wkl[(size_t)EDIM*EDIM];
__device__ __nv_bfloat16 g_wvh[(size_t)EDIM*EDIM], g_wvl[(size_t)EDIM*EDIM];
__device__ __nv_bfloat16 g_woh[(size_t)EDIM*EDIM], g_wol[(size_t)EDIM*EDIM];

// ---------------- PTX helpers (baseline sm_80-class; no 'a' variants) --------
__device__ __forceinline__ u32 s2u(const void* p) {
    u32 a; asm("{ .reg .u64 t; cvta.to.shared.u64 t, %1; cvt.u32.u64 %0, t; }" : "=r"(a) : "l"(p));
    return a;
}
__device__ __forceinline__ void cpa16(u32 dst, const void* src) {
    asm volatile("cp.async.cg.shared.global [%0], [%1], 16;" :: "r"(dst), "l"(src) : "memory");
}
__device__ __forceinline__ void cpa_commit() {
    asm volatile("cp.async.commit_group;" ::: "memory");
}
__device__ __forceinline__ void cpa_wait1() {
    asm volatile("cp.async.wait_group 1;" ::: "memory");
}
__device__ __forceinline__ void ldm4(u32* r, u32 addr) {
    asm volatile("ldmatrix.sync.aligned.m8n8.x4.shared.b16 {%0,%1,%2,%3}, [%4];"
                 : "=r"(r[0]), "=r"(r[1]), "=r"(r[2]), "=r"(r[3]) : "r"(addr));
}
__device__ __forceinline__ void mma_bf16(float* c, const u32* a, u32 b0, u32 b1) {
    asm volatile("mma.sync.aligned.m16n8k16.row.col.f32.bf16.bf16.f32 "
                 "{%0,%1,%2,%3}, {%4,%5,%6,%7}, {%8,%9}, {%0,%1,%2,%3};"
                 : "+f"(c[0]), "+f"(c[1]), "+f"(c[2]), "+f"(c[3])
                 : "r"(a[0]), "r"(a[1]), "r"(a[2]), "r"(a[3]), "r"(b0), "r"(b1));
}

// ============================================================================
// Tensor-core GEMM: C[m][n] = alpha*(sum_k A[m][k]*B[n][k] + bias[n])
// A,B bf16 hi/lo pairs; acc = Ah*Bh + Ah*Bl + Al*Bh in fp32 regs.
// CTA tile 128x256, BK=64; 8 warps, each 64x64 (2M x 4N layout).
// SMEM: row*128B, 16B-col swizzle c16 ^ (row&7); double buffer 2x96KB.
// ============================================================================
#define BM 128
#define BN 256
#define BK 64
#define NCHUNK (EDIM/BK)            // 16
#define TA_B (BM*BK*2)              // 16384 B per A sub-tile
#define TB_B (BN*BK*2)              // 32768 B per B sub-tile
#define BUF_B (2*TA_B + 2*TB_B)     // 98304 B: Ah, Al, Bh, Bl
#define SMEM_DYN (1024 + 2*BUF_B)   // 197632 B

__global__ void __launch_bounds__(256, 1)
tc_gemm(const __nv_bfloat16* __restrict__ Ah, const __nv_bfloat16* __restrict__ Al,
        const __nv_bfloat16* __restrict__ Bh, const __nv_bfloat16* __restrict__ Bl,
        const float* __restrict__ bias, float* __restrict__ C, float alpha)
{
    extern __shared__ char smem_raw[];
    const u32 bufbase = (s2u(smem_raw) + 1023u) & ~1023u;
    const int tid  = threadIdx.x;
    const int wid  = tid >> 5, lane = tid & 31;
    const int m0   = blockIdx.y * BM, n0 = blockIdx.x * BN;
    const int wm   = (wid & 1) * 64;      // warp M offset
    const int wn   = (wid >> 1) * 64;     // warp N offset

    const __nv_bfloat16* s0 = Ah + (size_t)m0 * EDIM;
    const __nv_bfloat16* s1 = Al + (size_t)m0 * EDIM;
    const __nv_bfloat16* s2 = Bh + (size_t)n0 * EDIM;
    const __nv_bfloat16* s3 = Bl + (size_t)n0 * EDIM;

    auto load_chunk = [&](int c, int buf) {
        const u32 base = bufbase + buf * BUF_B;
        const int k0 = c * BK;
        #pragma unroll
        for (int it = 0; it < 4; it++) {           // A: 128 rows x 8 segs
            int seg = tid + it * 256;
            int r   = seg >> 3;
            int c16 = seg & 7;
            u32 sw  = (u32)(r * 128 + 16 * (c16 ^ (r & 7)));
            size_t g = (size_t)r * EDIM + k0 + c16 * 8;
            cpa16(base + sw,        s0 + g);
            cpa16(base + TA_B + sw, s1 + g);
        }
        #pragma unroll
        for (int it = 0; it < 8; it++) {           // B: 256 rows x 8 segs
            int seg = tid + it * 256;
            int r   = seg >> 3;
            int c16 = seg & 7;
            u32 sw  = (u32)(r * 128 + 16 * (c16 ^ (r & 7)));
            size_t g = (size_t)r * EDIM + k0 + c16 * 8;
            cpa16(base + 2*TA_B + sw,        s2 + g);
            cpa16(base + 2*TA_B + TB_B + sw, s3 + g);
        }
    };

    float acc[32][4];
    #pragma unroll
    for (int i = 0; i < 32; i++)
        #pragma unroll
        for (int j = 0; j < 4; j++) acc[i][j] = 0.0f;

    load_chunk(0, 0); cpa_commit();
    load_chunk(1, 1); cpa_commit();

    const int a_row = ((lane >> 3) & 1) * 8 + (lane & 7);
    const int a_cs  = (lane >> 4) & 1;
    const int b_row = ((lane >> 4) & 1) * 8 + (lane & 7);
    const int b_cs  = (lane >> 3) & 1;

    for (int c = 0; c < NCHUNK; c++) {
        cpa_wait1();
        __syncthreads();

        const u32 base = bufbase + (c & 1) * BUF_B;
        const u32 bAh = base, bAl = base + TA_B;
        const u32 bBh = base + 2*TA_B, bBl = base + 2*TA_B + TB_B;

        #pragma unroll
        for (int ks4 = 0; ks4 < 4; ks4++) {        // four k16 steps in BK=64
            const int ks = 2 * ks4;
            u32 ah[4][4], al[4][4];
            #pragma unroll
            for (int mt = 0; mt < 4; mt++) {
                int row = wm + mt * 16 + a_row;
                u32 off = (u32)(row * 128 + 16 * ((ks + a_cs) ^ (row & 7)));
                ldm4(ah[mt], bAh + off);
                ldm4(al[mt], bAl + off);
            }
            #pragma unroll
            for (int nt2 = 0; nt2 < 4; nt2++) {    // four n16 groups
                int row = wn + nt2 * 16 + b_row;
                u32 off = (u32)(row * 128 + 16 * ((ks + b_cs) ^ (row & 7)));
                u32 bh[4], bl[4];
                ldm4(bh, bBh + off);
                ldm4(bl, bBl + off);
                #pragma unroll
                for (int jj = 0; jj < 2; jj++)
                    #pragma unroll
                    for (int mt = 0; mt < 4; mt++) {
                        float* cc = acc[(nt2*2 + jj)*4 + mt];
                        mma_bf16(cc, ah[mt], bh[2*jj], bh[2*jj+1]);
                        mma_bf16(cc, ah[mt], bl[2*jj], bl[2*jj+1]);
                        mma_bf16(cc, al[mt], bh[2*jj], bh[2*jj+1]);
                    }
            }
        }
        __syncthreads();
        if (c + 2 < NCHUNK) load_chunk(c + 2, c & 1);
        cpa_commit();                              // keep group-count invariant
    }

    // epilogue
    const int qr = lane >> 2;            // 0..7
    const int qc = (lane & 3) * 2;       // 0,2,4,6
    #pragma unroll
    for (int nt = 0; nt < 8; nt++) {
        const int col = n0 + wn + nt*8 + qc;
        const float b0 = bias[col], b1 = bias[col+1];
        #pragma unroll
        for (int mt = 0; mt < 4; mt++) {
            const float* cc = acc[nt*4 + mt];
            const int r0 = m0 + wm + mt*16 + qr;
            *(float2*)(C + (size_t)r0       * EDIM + col) =
                make_float2(alpha*(cc[0]+b0), alpha*(cc[1]+b1));
            *(float2*)(C + (size_t)(r0 + 8) * EDIM + col) =
                make_float2(alpha*(cc[2]+b0), alpha*(cc[3]+b1));
        }
    }
}

// ============================================================================
// fp32 -> bf16 hi/lo split
// ============================================================================
__global__ void __launch_bounds__(256)
cvt_hilo(const float* __restrict__ X, __nv_bfloat16* __restrict__ H,
         __nv_bfloat16* __restrict__ L, int n4)
{
    int i = blockIdx.x * blockDim.x + threadIdx.x;
    if (i >= n4) return;
    float4 x = ((const float4*)X)[i];
    __nv_bfloat16 h0 = __float2bfloat16(x.x), h1 = __float2bfloat16(x.y);
    __nv_bfloat16 h2 = __float2bfloat16(x.z), h3 = __float2bfloat16(x.w);
    __nv_bfloat16 l0 = __float2bfloat16(x.x - __bfloat162float(h0));
    __nv_bfloat16 l1 = __float2bfloat16(x.y - __bfloat162float(h1));
    __nv_bfloat16 l2 = __float2bfloat16(x.z - __bfloat162float(h2));
    __nv_bfloat16 l3 = __float2bfloat16(x.w - __bfloat162float(h3));
    __nv_bfloat162 hA; hA.x = h0; hA.y = h1;
    __nv_bfloat162 hB; hB.x = h2; hB.y = h3;
    __nv_bfloat162 lA; lA.x = l0; lA.y = l1;
    __nv_bfloat162 lB; lB.x = l2; lB.y = l3;
    ((__nv_bfloat162*)H)[2*i]   = hA; ((__nv_bfloat162*)H)[2*i+1] = hB;
    ((__nv_bfloat162*)L)[2*i]   = lA; ((__nv_bfloat162*)L)[2*i+1] = lB;
}

// ============================================================================
// Local chunked relu-attention (R3 version)
// ============================================================================
#define SWZC(g,e) ((((g) ^ ((e) & 15)) << 2))

__global__ void __launch_bounds__(256)
local_attn(const float* __restrict__ Q, const float* __restrict__ Km,
           const float* __restrict__ Vm, float* __restrict__ O)
{
    __shared__ float qT[64][64];
    __shared__ float kv[64][64];
    __shared__ float ss[64][64];
    const int w   = blockIdx.x;
    const int h   = blockIdx.y;
    const int tid = threadIdx.x;
    const int tx  = tid & 15;
    const int ty  = tid >> 4;
    const int cb  = h * HD;

    #pragma unroll
    for (int l = 0; l < 4; l++) {
        int idx = tid + l * 256;
        int i   = idx >> 4;
        int e4  = (idx & 15) << 2;
        float4 t = *(const float4*)(Q + (size_t)(w*CH + i)*EDIM + cb + e4);
        int g = i >> 2, im = i & 3;
        qT[e4+0][SWZC(g, e4+0) + im] = t.x;
        qT[e4+1][SWZC(g, e4+1) + im] = t.y;
        qT[e4+2][SWZC(g, e4+2) + im] = t.z;
        qT[e4+3][SWZC(g, e4+3) + im] = t.w;
    }

    float o[4][4] = {};

    for (int cw = w - 1; cw <= w + 1; cw++) {
        if (cw < 0 || cw >= NW) continue;
        __syncthreads();

        #pragma unroll
        for (int l = 0; l < 4; l++) {
            int idx = tid + l * 256;
            int j   = idx >> 4;
            int e4  = (idx & 15) << 2;
            float4 t = *(const float4*)(Km + (size_t)(cw*CH + j)*EDIM + cb + e4);
            int g = j >> 2, jm = j & 3;
            kv[e4+0][SWZC(g, e4+0) + jm] = t.x;
            kv[e4+1][SWZC(g, e4+1) + jm] = t.y;
            kv[e4+2][SWZC(g, e4+2) + jm] = t.z;
            kv[e4+3][SWZC(g, e4+3) + jm] = t.w;
        }
        __syncthreads();

        float s[4][4] = {};
        #pragma unroll 8
        for (int e = 0; e < 64; e++) {
            float4 a = *(const float4*)&qT[e][SWZC(ty, e)];
            float4 b = *(const float4*)&kv[e][SWZC(tx, e)];
            float av[4] = {a.x, a.y, a.z, a.w};
            float bv[4] = {b.x, b.y, b.z, b.w};
            #pragma unroll
            for (int rr = 0; rr < 4; rr++)
                #pragma unroll
                for (int cc = 0; cc < 4; cc++)
                    s[rr][cc] += av[rr] * bv[cc];
        }
        #pragma unroll
        for (int rr = 0; rr < 4; rr++)
            #pragma unroll
            for (int cc = 0; cc < 4; cc++)
                ss[ty*4+rr][tx*4+cc] = fmaxf(s[rr][cc], 0.0f);
        __syncthreads();

        #pragma unroll
        for (int l = 0; l < 4; l++) {
            int idx = tid + l * 256;
            int j   = idx >> 4;
            int e4  = (idx & 15) << 2;
            *(float4*)&kv[j][e4] =
                *(const float4*)(Vm + (size_t)(cw*CH + j)*EDIM + cb + e4);
        }
        __syncthreads();

        #pragma unroll 8
        for (int j = 0; j < 64; j++) {
            float4 vv = *(const float4*)&kv[j][tx*4];
            float s0 = ss[ty*4+0][j];
            float s1 = ss[ty*4+1][j];
            float s2 = ss[ty*4+2][j];
            float s3 = ss[ty*4+3][j];
            o[0][0] += s0*vv.x; o[0][1] += s0*vv.y; o[0][2] += s0*vv.z; o[0][3] += s0*vv.w;
            o[1][0] += s1*vv.x; o[1][1] += s1*vv.y; o[1][2] += s1*vv.z; o[1][3] += s1*vv.w;
            o[2][0] += s2*vv.x; o[2][1] += s2*vv.y; o[2][2] += s2*vv.z; o[2][3] += s2*vv.w;
            o[3][0] += s3*vv.x; o[3][1] += s3*vv.y; o[3][2] += s3*vv.z; o[3][3] += s3*vv.w;
        }
    }

    #pragma unroll
    for (int rr = 0; rr < 4; rr++) {
        float4 t = make_float4(o[rr][0], o[rr][1], o[rr][2], o[rr][3]);
        *(float4*)(O + (size_t)(w*CH + ty*4 + rr)*EDIM + cb + tx*4) = t;
    }
}

// ============================================================================
// Gated RMSNorm -> bf16 hi/lo
// ============================================================================
__global__ void __launch_bounds__(256)
rms_gate_bf(const float* __restrict__ X, const float* __restrict__ sc,
            const float* __restrict__ gt, __nv_bfloat16* __restrict__ H,
            __nv_bfloat16* __restrict__ L)
{
    __shared__ float red[8];
    const int row = blockIdx.x;
    const int tid = threadIdx.x;
    float4 x = ((const float4*)(X + (size_t)row * EDIM))[tid];
    float ssq = x.x*x.x + x.y*x.y + x.z*x.z + x.w*x.w;
    #pragma unroll
    for (int d = 16; d; d >>= 1) ssq += __shfl_xor_sync(0xffffffffu, ssq, d);
    if ((tid & 31) == 0) red[tid >> 5] = ssq;
    __syncthreads();
    if (tid < 32) {
        float t = (tid < 8) ? red[tid] : 0.0f;
        #pragma unroll
        for (int d = 4; d; d >>= 1) t += __shfl_xor_sync(0xffffffffu, t, d);
        if (tid == 0) red[0] = t;
    }
    __syncthreads();
    const float rms = sqrtf(red[0] * (1.0f / EDIM));
    const float inv = 1.0f / (rms + 1e-8f);
    const int c = tid << 2;
    float4 s4 = *(const float4*)(sc + c);
    float4 g4 = *(const float4*)(gt + c);
    float y0 = s4.x * x.x * inv * (1.0f / (1.0f + __expf(-g4.x * x.x)));
    float y1 = s4.y * x.y * inv * (1.0f / (1.0f + __expf(-g4.y * x.y)));
    float y2 = s4.z * x.z * inv * (1.0f / (1.0f + __expf(-g4.z * x.z)));
    float y3 = s4.w * x.w * inv * (1.0f / (1.0f + __expf(-g4.w * x.w)));
    __nv_bfloat16 h0 = __float2bfloat16(y0), h1 = __float2bfloat16(y1);
    __nv_bfloat16 h2 = __float2bfloat16(y2), h3 = __float2bfloat16(y3);
    __nv_bfloat16 l0 = __float2bfloat16(y0 - __bfloat162float(h0));
    __nv_bfloat16 l1 = __float2bfloat16(y1 - __bfloat162float(h1));
    __nv_bfloat16 l2 = __float2bfloat16(y2 - __bfloat162float(h2));
    __nv_bfloat16 l3 = __float2bfloat16(y3 - __bfloat162float(h3));
    size_t base = (size_t)row * EDIM + c;
    __nv_bfloat162 hA; hA.x = h0; hA.y = h1;
    __nv_bfloat162 hB; hB.x = h2; hB.y = h3;
    __nv_bfloat162 lA; lA.x = l0; lA.y = l1;
    __nv_bfloat162 lB; lB.x = l2; lB.y = l3;
    *(__nv_bfloat162*)(H + base)     = hA;
    *(__nv_bfloat162*)(H + base + 2) = hB;
    *(__nv_bfloat162*)(L + base)     = lA;
    *(__nv_bfloat162*)(L + base + 2) = lB;
}

// ============================================================================
extern "C" void kernel_launch(void* const* d_in, const int* in_sizes, int n_in,
                              void* d_out, int out_size)
{
    const float* query = (const float*)d_in[0];
    const float* key_  = (const float*)d_in[1];
    const float* value = (const float*)d_in[2];
    const float* w_q   = (const float*)d_in[3];
    const float* b_q   = (const float*)d_in[4];
    const float* w_k   = (const float*)d_in[5];
    const float* b_k   = (const float*)d_in[6];
    const float* w_v   = (const float*)d_in[7];
    const float* b_v   = (const float*)d_in[8];
    const float* w_o   = (const float*)d_in[9];
    const float* b_o   = (const float*)d_in[10];
    const float* nsc   = (const float*)d_in[11];
    const float* ngt   = (const float*)d_in[12];
    float* out = (float*)d_out;

    void *pq, *pk, *pv, *pa;
    void *paqh, *paql, *pakh, *pakl, *pavh, *pavl;
    void *pwqh, *pwql, *pwkh, *pwkl, *pwvh, *pwvl, *pwoh, *pwol;
    cudaGetSymbolAddress(&pq,  g_q);
    cudaGetSymbolAddress(&pk,  g_k);
    cudaGetSymbolAddress(&pv,  g_v);
    cudaGetSymbolAddress(&pa,  g_att);
    cudaGetSymbolAddress(&paqh, g_aqh); cudaGetSymbolAddress(&paql, g_aql);
    cudaGetSymbolAddress(&pakh, g_akh); cudaGetSymbolAddress(&pakl, g_akl);
    cudaGetSymbolAddress(&pavh, g_avh); cudaGetSymbolAddress(&pavl, g_avl);
    cudaGetSymbolAddress(&pwqh, g_wqh); cudaGetSymbolAddress(&pwql, g_wql);
    cudaGetSymbolAddress(&pwkh, g_wkh); cudaGetSymbolAddress(&pwkl, g_wkl);
    cudaGetSymbolAddress(&pwvh, g_wvh); cudaGetSymbolAddress(&pwvl, g_wvl);
    cudaGetSymbolAddress(&pwoh, g_woh); cudaGetSymbolAddress(&pwol, g_wol);

    float* gq = (float*)pq;  float* gk = (float*)pk;
    float* gv = (float*)pv;  float* ga = (float*)pa;
    __nv_bfloat16 *aqh = (__nv_bfloat16*)paqh, *aql = (__nv_bfloat16*)paql;
    __nv_bfloat16 *akh = (__nv_bfloat16*)pakh, *akl = (__nv_bfloat16*)pakl;
    __nv_bfloat16 *avh = (__nv_bfloat16*)pavh, *avl = (__nv_bfloat16*)pavl;
    __nv_bfloat16 *wqh = (__nv_bfloat16*)pwqh, *wql = (__nv_bfloat16*)pwql;
    __nv_bfloat16 *wkh = (__nv_bfloat16*)pwkh, *wkl = (__nv_bfloat16*)pwkl;
    __nv_bfloat16 *wvh = (__nv_bfloat16*)pwvh, *wvl = (__nv_bfloat16*)pwvl;
    __nv_bfloat16 *woh = (__nv_bfloat16*)pwoh, *wol = (__nv_bfloat16*)pwol;

    cudaFuncSetAttribute(tc_gemm, cudaFuncAttributeMaxDynamicSharedMemorySize, SMEM_DYN);

    const dim3 ggrd(EDIM/BN, LSEQ/BM);   // (4, 64)
    const int nA4 = LSEQ*EDIM/4;
    const int nW4 = EDIM*EDIM/4;
    const float scaling = 0.125f;        // HD^-0.5

    // all conversions up front (back-to-back, no GEMM interleave)
    cvt_hilo<<<nA4/256, 256>>>(query, aqh, aql, nA4);
    cvt_hilo<<<nA4/256, 256>>>(key_,  akh, akl, nA4);
    cvt_hilo<<<nA4/256, 256>>>(value, avh, avl, nA4);
    cvt_hilo<<<nW4/256, 256>>>(w_q, wqh, wql, nW4);
    cvt_hilo<<<nW4/256, 256>>>(w_k, wkh, wkl, nW4);
    cvt_hilo<<<nW4/256, 256>>>(w_v, wvh, wvl, nW4);
    cvt_hilo<<<nW4/256, 256>>>(w_o, woh, wol, nW4);

    tc_gemm<<<ggrd, 256, SMEM_DYN>>>(aqh, aql, wqh, wql, b_q, gq, scaling);
    tc_gemm<<<ggrd, 256, SMEM_DYN>>>(akh, akl, wkh, wkl, b_k, gk, 1.0f);
    tc_gemm<<<ggrd, 256, SMEM_DYN>>>(avh, avl, wvh, wvl, b_v, gv, 1.0f);

    local_attn<<<dim3(NW, NH), 256>>>(gq, gk, gv, ga);

    rms_gate_bf<<<LSEQ, 256>>>(ga, nsc, ngt, aqh, aql);

    tc_gemm<<<ggrd, 256, SMEM_DYN>>>(aqh, aql, woh, wol, b_o, out, 1.0f);
}

// round 8
// speedup vs baseline: 3.0888x; 1.1647x over previous
#include <cuda_runtime.h>
#include <cuda_bf16.h>
#include <math.h>

#define LSEQ 8192
#define EDIM 1024
#define NH   16
#define HD   64
#define CH   64
#define NW   (LSEQ/CH)

typedef unsigned int       u32;
typedef unsigned long long u64;

// ---------------- scratch (__device__ globals; no allocation) ----------------
__device__ float g_att[(size_t)LSEQ*EDIM];
// converted inputs (act + weights)
__device__ __nv_bfloat16 g_aqh[(size_t)LSEQ*EDIM], g_aql[(size_t)LSEQ*EDIM];
__device__ __nv_bfloat16 g_akh[(size_t)LSEQ*EDIM], g_akl[(size_t)LSEQ*EDIM];
__device__ __nv_bfloat16 g_avh[(size_t)LSEQ*EDIM], g_avl[(size_t)LSEQ*EDIM];
__device__ __nv_bfloat16 g_wqh[(size_t)EDIM*EDIM], g_wql[(size_t)EDIM*EDIM];
__device__ __nv_bfloat16 g_wkh[(size_t)EDIM*EDIM], g_wkl[(size_t)EDIM*EDIM];
__device__ __nv_bfloat16 g_wvh[(size_t)EDIM*EDIM], g_wvl[(size_t)EDIM*EDIM];
__device__ __nv_bfloat16 g_woh[(size_t)EDIM*EDIM], g_wol[(size_t)EDIM*EDIM];
// projection outputs (bf16 hi/lo, feed attention)
__device__ __nv_bfloat16 g_qh[(size_t)LSEQ*EDIM], g_ql[(size_t)LSEQ*EDIM];
__device__ __nv_bfloat16 g_kh[(size_t)LSEQ*EDIM], g_kl[(size_t)LSEQ*EDIM];
__device__ __nv_bfloat16 g_vh[(size_t)LSEQ*EDIM], g_vl[(size_t)LSEQ*EDIM];

// ---------------- PTX helpers (baseline sm_80-class) ----------------
__device__ __forceinline__ u32 s2u(const void* p) {
    u32 a; asm("{ .reg .u64 t; cvta.to.shared.u64 t, %1; cvt.u32.u64 %0, t; }" : "=r"(a) : "l"(p));
    return a;
}
__device__ __forceinline__ void cpa16(u32 dst, const void* src) {
    asm volatile("cp.async.cg.shared.global [%0], [%1], 16;" :: "r"(dst), "l"(src) : "memory");
}
__device__ __forceinline__ void cpa_commit() {
    asm volatile("cp.async.commit_group;" ::: "memory");
}
__device__ __forceinline__ void cpa_wait1() {
    asm volatile("cp.async.wait_group 1;" ::: "memory");
}
__device__ __forceinline__ void cpa_wait0() {
    asm volatile("cp.async.wait_group 0;" ::: "memory");
}
__device__ __forceinline__ void ldm4(u32* r, u32 addr) {
    asm volatile("ldmatrix.sync.aligned.m8n8.x4.shared.b16 {%0,%1,%2,%3}, [%4];"
                 : "=r"(r[0]), "=r"(r[1]), "=r"(r[2]), "=r"(r[3]) : "r"(addr));
}
__device__ __forceinline__ void ldm4t(u32* r, u32 addr) {
    asm volatile("ldmatrix.sync.aligned.m8n8.x4.trans.shared.b16 {%0,%1,%2,%3}, [%4];"
                 : "=r"(r[0]), "=r"(r[1]), "=r"(r[2]), "=r"(r[3]) : "r"(addr));
}
__device__ __forceinline__ void mma_bf16(float* c, const u32* a, u32 b0, u32 b1) {
    asm volatile("mma.sync.aligned.m16n8k16.row.col.f32.bf16.bf16.f32 "
                 "{%0,%1,%2,%3}, {%4,%5,%6,%7}, {%8,%9}, {%0,%1,%2,%3};"
                 : "+f"(c[0]), "+f"(c[1]), "+f"(c[2]), "+f"(c[3])
                 : "r"(a[0]), "r"(a[1]), "r"(a[2]), "r"(a[3]), "r"(b0), "r"(b1));
}
__device__ __forceinline__ u32 packbf2(float lo, float hi) {
    __nv_bfloat162 h = __float22bfloat162_rn(make_float2(lo, hi));
    return *(u32*)&h;
}

// ============================================================================
// Tensor-core GEMM: 3-product bf16 hi/lo, fp32 acc. CTA 128x256, 8 warps 64x64.
// Epilogue: fp32 C (bf16out=0) or bf16 hi/lo pair (bf16out=1).
// ============================================================================
#define BM 128
#define BN 256
#define BK 64
#define NCHUNK (EDIM/BK)
#define TA_B (BM*BK*2)
#define TB_B (BN*BK*2)
#define BUF_B (2*TA_B + 2*TB_B)
#define SMEM_DYN (1024 + 2*BUF_B)

__global__ void __launch_bounds__(256, 1)
tc_gemm(const __nv_bfloat16* __restrict__ Ah, const __nv_bfloat16* __restrict__ Al,
        const __nv_bfloat16* __restrict__ Bh, const __nv_bfloat16* __restrict__ Bl,
        const float* __restrict__ bias, float* __restrict__ C,
        __nv_bfloat16* __restrict__ Ho, __nv_bfloat16* __restrict__ Lo,
        float alpha, int bf16out)
{
    extern __shared__ char smem_raw[];
    const u32 bufbase = (s2u(smem_raw) + 1023u) & ~1023u;
    const int tid  = threadIdx.x;
    const int wid  = tid >> 5, lane = tid & 31;
    const int m0   = blockIdx.y * BM, n0 = blockIdx.x * BN;
    const int wm   = (wid & 1) * 64;
    const int wn   = (wid >> 1) * 64;

    const __nv_bfloat16* s0 = Ah + (size_t)m0 * EDIM;
    const __nv_bfloat16* s1 = Al + (size_t)m0 * EDIM;
    const __nv_bfloat16* s2 = Bh + (size_t)n0 * EDIM;
    const __nv_bfloat16* s3 = Bl + (size_t)n0 * EDIM;

    auto load_chunk = [&](int c, int buf) {
        const u32 base = bufbase + buf * BUF_B;
        const int k0 = c * BK;
        #pragma unroll
        for (int it = 0; it < 4; it++) {
            int seg = tid + it * 256;
            int r = seg >> 3, c16 = seg & 7;
            u32 sw = (u32)(r * 128 + 16 * (c16 ^ (r & 7)));
            size_t g = (size_t)r * EDIM + k0 + c16 * 8;
            cpa16(base + sw,        s0 + g);
            cpa16(base + TA_B + sw, s1 + g);
        }
        #pragma unroll
        for (int it = 0; it < 8; it++) {
            int seg = tid + it * 256;
            int r = seg >> 3, c16 = seg & 7;
            u32 sw = (u32)(r * 128 + 16 * (c16 ^ (r & 7)));
            size_t g = (size_t)r * EDIM + k0 + c16 * 8;
            cpa16(base + 2*TA_B + sw,        s2 + g);
            cpa16(base + 2*TA_B + TB_B + sw, s3 + g);
        }
    };

    float acc[32][4];
    #pragma unroll
    for (int i = 0; i < 32; i++)
        #pragma unroll
        for (int j = 0; j < 4; j++) acc[i][j] = 0.0f;

    load_chunk(0, 0); cpa_commit();
    load_chunk(1, 1); cpa_commit();

    const int a_row = ((lane >> 3) & 1) * 8 + (lane & 7);
    const int a_cs  = (lane >> 4) & 1;
    const int b_row = ((lane >> 4) & 1) * 8 + (lane & 7);
    const int b_cs  = (lane >> 3) & 1;

    for (int c = 0; c < NCHUNK; c++) {
        cpa_wait1();
        __syncthreads();

        const u32 base = bufbase + (c & 1) * BUF_B;
        const u32 bAh = base, bAl = base + TA_B;
        const u32 bBh = base + 2*TA_B, bBl = base + 2*TA_B + TB_B;

        #pragma unroll
        for (int ks4 = 0; ks4 < 4; ks4++) {
            const int ks = 2 * ks4;
            u32 ah[4][4], al[4][4];
            #pragma unroll
            for (int mt = 0; mt < 4; mt++) {
                int row = wm + mt * 16 + a_row;
                u32 off = (u32)(row * 128 + 16 * ((ks + a_cs) ^ (row & 7)));
                ldm4(ah[mt], bAh + off);
                ldm4(al[mt], bAl + off);
            }
            #pragma unroll
            for (int nt2 = 0; nt2 < 4; nt2++) {
                int row = wn + nt2 * 16 + b_row;
                u32 off = (u32)(row * 128 + 16 * ((ks + b_cs) ^ (row & 7)));
                u32 bh[4], bl[4];
                ldm4(bh, bBh + off);
                ldm4(bl, bBl + off);
                #pragma unroll
                for (int jj = 0; jj < 2; jj++)
                    #pragma unroll
                    for (int mt = 0; mt < 4; mt++) {
                        float* cc = acc[(nt2*2 + jj)*4 + mt];
                        mma_bf16(cc, ah[mt], bh[2*jj], bh[2*jj+1]);
                        mma_bf16(cc, ah[mt], bl[2*jj], bl[2*jj+1]);
                        mma_bf16(cc, al[mt], bh[2*jj], bh[2*jj+1]);
                    }
            }
        }
        __syncthreads();
        if (c + 2 < NCHUNK) load_chunk(c + 2, c & 1);
        cpa_commit();
    }

    const int qr = lane >> 2;
    const int qc = (lane & 3) * 2;
    #pragma unroll
    for (int nt = 0; nt < 8; nt++) {
        const int col = n0 + wn + nt*8 + qc;
        const float b0 = bias[col], b1 = bias[col+1];
        #pragma unroll
        for (int mt = 0; mt < 4; mt++) {
            const float* cc = acc[nt*4 + mt];
            const int r0 = m0 + wm + mt*16 + qr;
            float y00 = alpha*(cc[0]+b0), y01 = alpha*(cc[1]+b1);
            float y10 = alpha*(cc[2]+b0), y11 = alpha*(cc[3]+b1);
            if (!bf16out) {
                *(float2*)(C + (size_t)r0       * EDIM + col) = make_float2(y00, y01);
                *(float2*)(C + (size_t)(r0 + 8) * EDIM + col) = make_float2(y10, y11);
            } else {
                u32 h0 = packbf2(y00, y01);
                u32 h1 = packbf2(y10, y11);
                __nv_bfloat162 H0 = *(__nv_bfloat162*)&h0, H1 = *(__nv_bfloat162*)&h1;
                u32 l0 = packbf2(y00 - __bfloat162float(H0.x), y01 - __bfloat162float(H0.y));
                u32 l1 = packbf2(y10 - __bfloat162float(H1.x), y11 - __bfloat162float(H1.y));
                *(u32*)(Ho + (size_t)r0       * EDIM + col) = h0;
                *(u32*)(Ho + (size_t)(r0 + 8) * EDIM + col) = h1;
                *(u32*)(Lo + (size_t)r0       * EDIM + col) = l0;
                *(u32*)(Lo + (size_t)(r0 + 8) * EDIM + col) = l1;
            }
        }
    }
}

// ============================================================================
// fp32 -> bf16 hi/lo split
// ============================================================================
__global__ void __launch_bounds__(256)
cvt_hilo(const float* __restrict__ X, __nv_bfloat16* __restrict__ H,
         __nv_bfloat16* __restrict__ L, int n4)
{
    int i = blockIdx.x * blockDim.x + threadIdx.x;
    if (i >= n4) return;
    float4 x = ((const float4*)X)[i];
    u32 hA = packbf2(x.x, x.y), hB = packbf2(x.z, x.w);
    __nv_bfloat162 HA = *(__nv_bfloat162*)&hA, HB = *(__nv_bfloat162*)&hB;
    u32 lA = packbf2(x.x - __bfloat162float(HA.x), x.y - __bfloat162float(HA.y));
    u32 lB = packbf2(x.z - __bfloat162float(HB.x), x.w - __bfloat162float(HB.y));
    ((u32*)H)[2*i] = hA; ((u32*)H)[2*i+1] = hB;
    ((u32*)L)[2*i] = lA; ((u32*)L)[2*i+1] = lB;
}

// ============================================================================
// Tensor-core local attention. Block=(window,head), 4 warps, warp = 16 q-rows.
// Per chunk cw in {w-1,w,w+1}: S = relu(Q K^T) via mma (hi/lo 3-prod),
// C-frag reused as A-frag (bf16x2 repack), O += S V via mma with
// ldmatrix.x4.trans B fragments of v[j][e]. SMEM exactly 48KB static.
// ============================================================================
__global__ void __launch_bounds__(128)
att_mma(const __nv_bfloat16* __restrict__ Qh, const __nv_bfloat16* __restrict__ Ql,
        const __nv_bfloat16* __restrict__ Kh, const __nv_bfloat16* __restrict__ Kl,
        const __nv_bfloat16* __restrict__ Vh, const __nv_bfloat16* __restrict__ Vl,
        float* __restrict__ O)
{
    __shared__ __align__(1024) char smem[6 * 8192];   // QH QL KH KL VH VL
    const u32 sb = s2u(smem);
    const u32 QH = sb, QL = sb + 8192, KH = sb + 16384, KL = sb + 24576;
    const u32 VH = sb + 32768, VL = sb + 40960;

    const int w = blockIdx.x, h = blockIdx.y;
    const int tid = threadIdx.x;
    const int wid = tid >> 5, lane = tid & 31;
    const int cb  = h * HD;

    // load q tile (64 rows x 64 cols bf16, hi+lo)
    #pragma unroll
    for (int it = 0; it < 4; it++) {
        int seg = tid + it * 128;          // 0..511
        int r = seg >> 3, c16 = seg & 7;
        u32 sw = (u32)(r * 128 + 16 * (c16 ^ (r & 7)));
        size_t g = (size_t)(w*CH + r) * EDIM + cb + c16 * 8;
        cpa16(QH + sw, Qh + g);
        cpa16(QL + sw, Ql + g);
    }
    cpa_commit();

    float o[8][4];
    #pragma unroll
    for (int i = 0; i < 8; i++)
        #pragma unroll
        for (int j = 0; j < 4; j++) o[i][j] = 0.0f;

    const int a_row = ((lane >> 3) & 1) * 8 + (lane & 7);
    const int a_cs  = (lane >> 4) & 1;
    const int b_row = ((lane >> 4) & 1) * 8 + (lane & 7);
    const int b_cs  = (lane >> 3) & 1;
    // trans-load lane geometry for v[j][e]
    const int t_jrow = (lane & 7) + ((lane >> 3) & 1) * 8;
    const int t_e16  = (lane >> 4) & 1;

    for (int cw = w - 1; cw <= w + 1; cw++) {
        if (cw < 0 || cw >= NW) continue;
        __syncthreads();                       // prior-iter readers done
        #pragma unroll
        for (int it = 0; it < 4; it++) {
            int seg = tid + it * 128;
            int r = seg >> 3, c16 = seg & 7;
            u32 sw = (u32)(r * 128 + 16 * (c16 ^ (r & 7)));
            size_t g = (size_t)(cw*CH + r) * EDIM + cb + c16 * 8;
            cpa16(KH + sw, Kh + g);
            cpa16(KL + sw, Kl + g);
            cpa16(VH + sw, Vh + g);
            cpa16(VL + sw, Vl + g);
        }
        cpa_commit();
        cpa_wait0();                           // also covers q on first pass
        __syncthreads();

        // ---- scores: sc (m16 x 64) = q(16x64) @ k(64x64)^T, hi/lo 3-product
        float sc[8][4];
        #pragma unroll
        for (int i = 0; i < 8; i++)
            #pragma unroll
            for (int j = 0; j < 4; j++) sc[i][j] = 0.0f;

        #pragma unroll
        for (int ks4 = 0; ks4 < 4; ks4++) {    // k-dim (e) 16 per step
            const int ks = 2 * ks4;
            u32 ah[4], al[4];
            {
                int row = wid * 16 + a_row;
                u32 off = (u32)(row * 128 + 16 * ((ks + a_cs) ^ (row & 7)));
                ldm4(ah, QH + off);
                ldm4(al, QL + off);
            }
            #pragma unroll
            for (int jg = 0; jg < 4; jg++) {   // n-dim (j) 16 per group
                int row = jg * 16 + b_row;
                u32 off = (u32)(row * 128 + 16 * ((ks + b_cs) ^ (row & 7)));
                u32 bh[4], bl[4];
                ldm4(bh, KH + off);
                ldm4(bl, KL + off);
                #pragma unroll
                for (int jj = 0; jj < 2; jj++) {
                    float* cc = sc[jg*2 + jj];
                    mma_bf16(cc, ah, bh[2*jj], bh[2*jj+1]);
                    mma_bf16(cc, ah, bl[2*jj], bl[2*jj+1]);
                    mma_bf16(cc, al, bh[2*jj], bh[2*jj+1]);
                }
            }
        }

        // ---- relu + split, repack C-frag -> A-frag (k = j)
        u32 pah[4][4], pal[4][4];
        #pragma unroll
        for (int t = 0; t < 8; t++)
            #pragma unroll
            for (int r = 0; r < 4; r++) sc[t][r] = fmaxf(sc[t][r], 0.0f);
        #pragma unroll
        for (int ks = 0; ks < 4; ks++) {
            #pragma unroll
            for (int half = 0; half < 2; half++) {     // j-tile 2ks+half
                const float* s0 = sc[2*ks + half];
                u32 h0 = packbf2(s0[0], s0[1]);        // row qr
                u32 h1 = packbf2(s0[2], s0[3]);        // row qr+8
                __nv_bfloat162 H0 = *(__nv_bfloat162*)&h0, H1 = *(__nv_bfloat162*)&h1;
                u32 l0 = packbf2(s0[0] - __bfloat162float(H0.x), s0[1] - __bfloat162float(H0.y));
                u32 l1 = packbf2(s0[2] - __bfloat162float(H1.x), s0[3] - __bfloat162float(H1.y));
                pah[ks][half*2]     = h0;  pah[ks][half*2 + 1] = h1;
                pal[ks][half*2]     = l0;  pal[ks][half*2 + 1] = l1;
            }
        }

        // ---- PV: o(16 x 64) += s(16x64) @ v(64x64); B = v^T via ldmatrix.trans
        #pragma unroll
        for (int ks = 0; ks < 4; ks++) {       // k-dim (j) 16 per step
            const int j0 = ks * 16;
            #pragma unroll
            for (int eg = 0; eg < 4; eg++) {   // e16 groups
                int jrow = j0 + t_jrow;
                int c16  = eg * 2 + t_e16;
                u32 off  = (u32)(jrow * 128 + 16 * (c16 ^ (jrow & 7)));
                u32 vh4[4], vl4[4];
                ldm4t(vh4, VH + off);
                ldm4t(vl4, VL + off);
                #pragma unroll
                for (int half = 0; half < 2; half++) {
                    float* cc = o[eg*2 + half];
                    mma_bf16(cc, pah[ks], vh4[2*half], vh4[2*half+1]);
                    mma_bf16(cc, pah[ks], vl4[2*half], vl4[2*half+1]);
                    mma_bf16(cc, pal[ks], vh4[2*half], vh4[2*half+1]);
                }
            }
        }
    }

    // store O fragments (fp32)
    const int qr = lane >> 2;
    const int qc = (lane & 3) * 2;
    #pragma unroll
    for (int nt = 0; nt < 8; nt++) {
        const int col = cb + nt*8 + qc;
        const int r0  = w*CH + wid*16 + qr;
        *(float2*)(O + (size_t)r0       * EDIM + col) = make_float2(o[nt][0], o[nt][1]);
        *(float2*)(O + (size_t)(r0 + 8) * EDIM + col) = make_float2(o[nt][2], o[nt][3]);
    }
}

// ============================================================================
// Gated RMSNorm -> bf16 hi/lo
// ============================================================================
__global__ void __launch_bounds__(256)
rms_gate_bf(const float* __restrict__ X, const float* __restrict__ sc,
            const float* __restrict__ gt, __nv_bfloat16* __restrict__ H,
            __nv_bfloat16* __restrict__ L)
{
    __shared__ float red[8];
    const int row = blockIdx.x;
    const int tid = threadIdx.x;
    float4 x = ((const float4*)(X + (size_t)row * EDIM))[tid];
    float ssq = x.x*x.x + x.y*x.y + x.z*x.z + x.w*x.w;
    #pragma unroll
    for (int d = 16; d; d >>= 1) ssq += __shfl_xor_sync(0xffffffffu, ssq, d);
    if ((tid & 31) == 0) red[tid >> 5] = ssq;
    __syncthreads();
    if (tid < 32) {
        float t = (tid < 8) ? red[tid] : 0.0f;
        #pragma unroll
        for (int d = 4; d; d >>= 1) t += __shfl_xor_sync(0xffffffffu, t, d);
        if (tid == 0) red[0] = t;
    }
    __syncthreads();
    const float rms = sqrtf(red[0] * (1.0f / EDIM));
    const float inv = 1.0f / (rms + 1e-8f);
    const int c = tid << 2;
    float4 s4 = *(const float4*)(sc + c);
    float4 g4 = *(const float4*)(gt + c);
    float y0 = s4.x * x.x * inv * (1.0f / (1.0f + __expf(-g4.x * x.x)));
    float y1 = s4.y * x.y * inv * (1.0f / (1.0f + __expf(-g4.y * x.y)));
    float y2 = s4.z * x.z * inv * (1.0f / (1.0f + __expf(-g4.z * x.z)));
    float y3 = s4.w * x.w * inv * (1.0f / (1.0f + __expf(-g4.w * x.w)));
    u32 hA = packbf2(y0, y1), hB = packbf2(y2, y3);
    __nv_bfloat162 HA = *(__nv_bfloat162*)&hA, HB = *(__nv_bfloat162*)&hB;
    u32 lA = packbf2(y0 - __bfloat162float(HA.x), y1 - __bfloat162float(HA.y));
    u32 lB = packbf2(y2 - __bfloat162float(HB.x), y3 - __bfloat162float(HB.y));
    size_t base = (size_t)row * EDIM + c;
    *(u32*)(H + base)     = hA;  *(u32*)(H + base + 2) = hB;
    *(u32*)(L + base)     = lA;  *(u32*)(L + base + 2) = lB;
}

// ============================================================================
extern "C" void kernel_launch(void* const* d_in, const int* in_sizes, int n_in,
                              void* d_out, int out_size)
{
    const float* query = (const float*)d_in[0];
    const float* key_  = (const float*)d_in[1];
    const float* value = (const float*)d_in[2];
    const float* w_q   = (const float*)d_in[3];
    const float* b_q   = (const float*)d_in[4];
    const float* w_k   = (const float*)d_in[5];
    const float* b_k   = (const float*)d_in[6];
    const float* w_v   = (const float*)d_in[7];
    const float* b_v   = (const float*)d_in[8];
    const float* w_o   = (const float*)d_in[9];
    const float* b_o   = (const float*)d_in[10];
    const float* nsc   = (const float*)d_in[11];
    const float* ngt   = (const float*)d_in[12];
    float* out = (float*)d_out;

    void *pa;
    void *paqh,*paql,*pakh,*pakl,*pavh,*pavl;
    void *pwqh,*pwql,*pwkh,*pwkl,*pwvh,*pwvl,*pwoh,*pwol;
    void *pqh,*pql,*pkh,*pkl,*pvh,*pvl;
    cudaGetSymbolAddress(&pa,  g_att);
    cudaGetSymbolAddress(&paqh, g_aqh); cudaGetSymbolAddress(&paql, g_aql);
    cudaGetSymbolAddress(&pakh, g_akh); cudaGetSymbolAddress(&pakl, g_akl);
    cudaGetSymbolAddress(&pavh, g_avh); cudaGetSymbolAddress(&pavl, g_avl);
    cudaGetSymbolAddress(&pwqh, g_wqh); cudaGetSymbolAddress(&pwql, g_wql);
    cudaGetSymbolAddress(&pwkh, g_wkh); cudaGetSymbolAddress(&pwkl, g_wkl);
    cudaGetSymbolAddress(&pwvh, g_wvh); cudaGetSymbolAddress(&pwvl, g_wvl);
    cudaGetSymbolAddress(&pwoh, g_woh); cudaGetSymbolAddress(&pwol, g_wol);
    cudaGetSymbolAddress(&pqh, g_qh);   cudaGetSymbolAddress(&pql, g_ql);
    cudaGetSymbolAddress(&pkh, g_kh);   cudaGetSymbolAddress(&pkl, g_kl);
    cudaGetSymbolAddress(&pvh, g_vh);   cudaGetSymbolAddress(&pvl, g_vl);

    float* ga = (float*)pa;
    __nv_bfloat16 *aqh=(__nv_bfloat16*)paqh, *aql=(__nv_bfloat16*)paql;
    __nv_bfloat16 *akh=(__nv_bfloat16*)pakh, *akl=(__nv_bfloat16*)pakl;
    __nv_bfloat16 *avh=(__nv_bfloat16*)pavh, *avl=(__nv_bfloat16*)pavl;
    __nv_bfloat16 *wqh=(__nv_bfloat16*)pwqh, *wql=(__nv_bfloat16*)pwql;
    __nv_bfloat16 *wkh=(__nv_bfloat16*)pwkh, *wkl=(__nv_bfloat16*)pwkl;
    __nv_bfloat16 *wvh=(__nv_bfloat16*)pwvh, *wvl=(__nv_bfloat16*)pwvl;
    __nv_bfloat16 *woh=(__nv_bfloat16*)pwoh, *wol=(__nv_bfloat16*)pwol;
    __nv_bfloat16 *qh=(__nv_bfloat16*)pqh,   *ql=(__nv_bfloat16*)pql;
    __nv_bfloat16 *kh=(__nv_bfloat16*)pkh,   *kl=(__nv_bfloat16*)pkl;
    __nv_bfloat16 *vh=(__nv_bfloat16*)pvh,   *vl=(__nv_bfloat16*)pvl;

    cudaFuncSetAttribute(tc_gemm, cudaFuncAttributeMaxDynamicSharedMemorySize, SMEM_DYN);

    const dim3 ggrd(EDIM/BN, LSEQ/BM);
    const int nA4 = LSEQ*EDIM/4;
    const int nW4 = EDIM*EDIM/4;
    const float scaling = 0.125f;

    cvt_hilo<<<nA4/256, 256>>>(query, aqh, aql, nA4);
    cvt_hilo<<<nA4/256, 256>>>(key_,  akh, akl, nA4);
    cvt_hilo<<<nA4/256, 256>>>(value, avh, avl, nA4);
    cvt_hilo<<<nW4/256, 256>>>(w_q, wqh, wql, nW4);
    cvt_hilo<<<nW4/256, 256>>>(w_k, wkh, wkl, nW4);
    cvt_hilo<<<nW4/256, 256>>>(w_v, wvh, wvl, nW4);
    cvt_hilo<<<nW4/256, 256>>>(w_o, woh, wol, nW4);

    tc_gemm<<<ggrd, 256, SMEM_DYN>>>(aqh, aql, wqh, wql, b_q, nullptr, qh, ql, scaling, 1);
    tc_gemm<<<ggrd, 256, SMEM_DYN>>>(akh, akl, wkh, wkl, b_k, nullptr, kh, kl, 1.0f, 1);
    tc_gemm<<<ggrd, 256, SMEM_DYN>>>(avh, avl, wvh, wvl, b_v, nullptr, vh, vl, 1.0f, 1);

    att_mma<<<dim3(NW, NH), 128>>>(qh, ql, kh, kl, vh, vl, ga);

    rms_gate_bf<<<LSEQ, 256>>>(ga, nsc, ngt, aqh, aql);

    tc_gemm<<<ggrd, 256, SMEM_DYN>>>(aqh, aql, woh, wol, b_o, out, nullptr, nullptr, 1.0f, 0);
}